// round 12
// baseline (speedup 1.0000x reference)
#include <cuda_runtime.h>
#include <cuda_bf16.h>

#define D_DIM     128
#define N_RBF     50
#define KP        56            // MMA K padded to 7 x 8
#define E_TILE    64            // edges per tile
#define RBF_STRIDE 60           // conflict-free B-fragment banks
#define MSG_STRIDE 132          // conflict-free epilogue STS; 528B = 33*16 aligned
#define MAX_NODES 50000
#define CUTOFF_F  5.0f
#define PI_OVER_CUTOFF 0.62831853071795864769f

// scatter-sum accumulator (device global scratch; no cudaMalloc allowed)
__device__ float g_acc[(size_t)MAX_NODES * D_DIM];

// ---------------------------------------------------------------------------
// helpers
// ---------------------------------------------------------------------------
__device__ __forceinline__ unsigned cvt_tf32(float x) {
    unsigned r;
    asm("cvt.rna.tf32.f32 %0, %1;" : "=r"(r) : "f"(x));
    return r;
}
__device__ __forceinline__ void mma_tf32(float* acc, const unsigned* a,
                                         unsigned b0, unsigned b1) {
    asm("mma.sync.aligned.m16n8k8.row.col.f32.tf32.tf32.f32 "
        "{%0,%1,%2,%3},{%4,%5,%6,%7},{%8,%9},{%0,%1,%2,%3};"
        : "+f"(acc[0]), "+f"(acc[1]), "+f"(acc[2]), "+f"(acc[3])
        : "r"(a[0]), "r"(a[1]), "r"(a[2]), "r"(a[3]), "r"(b0), "r"(b1));
}

// ---------------------------------------------------------------------------
// Kernel 1: zero the accumulator
// ---------------------------------------------------------------------------
__global__ void zero_kernel(float4* a, int n4) {
    int i = blockIdx.x * blockDim.x + threadIdx.x;
    if (i < n4) a[i] = make_float4(0.f, 0.f, 0.f, 0.f);
}

// ---------------------------------------------------------------------------
// Kernel 2: edge kernel, TF32 MMA, double-buffered, E_TILE=64.
//   C[dim, edge] = W_e(A, 56 regs tf32) x rbf_tile(B, smem tf32).
//   Warp w owns dims [32w, 32w+32) for all 64 tile edges:
//   2 m-tiles x 8 n-tiles x 7 k-steps of m16n8k8.
//   Epilogue (fp32): (acc + b_e) * emb[type] * cutoff -> msg_sh -> float4 atomicAdd.
// ---------------------------------------------------------------------------
__global__ void __launch_bounds__(128) edge_kernel(
    const float* __restrict__ rbf,       // [E, 50]
    const float* __restrict__ dist,      // [E]
    const int*   __restrict__ src,       // [E]
    const int*   __restrict__ dst,       // [E]
    const int*   __restrict__ node_type, // [N]
    const float* __restrict__ emb,       // [100, 128]
    const float* __restrict__ W_e,       // [128, 50]
    const float* __restrict__ b_e,       // [128]
    int n_edges)
{
    __shared__ unsigned rbf_sh[2][E_TILE][RBF_STRIDE];
    __shared__ float    msg_sh[E_TILE][MSG_STRIDE];
    __shared__ float    w_sh[2][E_TILE];
    __shared__ int      dst_sh[2][E_TILE];
    __shared__ int      typ_sh[2][E_TILE];

    const int tid  = threadIdx.x;
    const int warp = tid >> 5;
    const int lane = tid & 31;
    const int g4   = lane >> 2;
    const int t4   = lane & 3;
    const int wbase = warp * 32;

    // A fragments: W_e as tf32, loaded once
    unsigned a_frag[2][7][4];
#pragma unroll
    for (int mt = 0; mt < 2; mt++)
#pragma unroll
        for (int ks = 0; ks < 7; ks++)
#pragma unroll
            for (int j = 0; j < 4; j++) {
                int d = wbase + mt * 16 + g4 + ((j & 1) ? 8 : 0);
                int k = ks * 8 + t4 + ((j >= 2) ? 4 : 0);
                float v = (k < N_RBF) ? W_e[d * N_RBF + k] : 0.f;
                a_frag[mt][ks][j] = cvt_tf32(v);
            }
    float be00 = b_e[wbase + g4];
    float be01 = b_e[wbase + g4 + 8];
    float be10 = b_e[wbase + 16 + g4];
    float be11 = b_e[wbase + 16 + g4 + 8];

    const int num_tiles = (n_edges + E_TILE - 1) / E_TILE;

    auto load_tile = [&](int t, int b) {
        const int e0 = t * E_TILE;
        const int nE = min(E_TILE, n_edges - e0);
        for (int i = tid; i < E_TILE * KP; i += 128) {
            int e = i / KP;
            int k = i - e * KP;
            float v = (k < N_RBF && e < nE) ? rbf[(size_t)(e0 + e) * N_RBF + k] : 0.f;
            rbf_sh[b][e][k] = cvt_tf32(v);
        }
        if (tid < E_TILE) {
            bool valid = tid < nE;
            float dd = valid ? dist[e0 + tid] : 1e9f;
            float w  = 0.5f * (__cosf(dd * PI_OVER_CUTOFF) + 1.0f);
            w_sh[b][tid]   = (dd < CUTOFF_F) ? w : 0.f;
            typ_sh[b][tid] = valid ? node_type[src[e0 + tid]] : 0;
            dst_sh[b][tid] = valid ? dst[e0 + tid] : 0;
        }
    };

    int p = 0;
    if (blockIdx.x < num_tiles) load_tile(blockIdx.x, 0);

    for (int tile = blockIdx.x; tile < num_tiles; tile += gridDim.x) {
        const int nE = min(E_TILE, n_edges - tile * E_TILE);

        __syncthreads();                 // buf[p] ready; msg_sh free

        const int next = tile + gridDim.x;
        if (next < num_tiles) load_tile(next, p ^ 1);   // overlap with MMA

        float acc[2][8][4];
#pragma unroll
        for (int mt = 0; mt < 2; mt++)
#pragma unroll
            for (int nt = 0; nt < 8; nt++)
#pragma unroll
                for (int j = 0; j < 4; j++) acc[mt][nt][j] = 0.f;

#pragma unroll
        for (int ntp = 0; ntp < 4; ntp++) {
            unsigned bfr[2][7][2];
#pragma unroll
            for (int ntl = 0; ntl < 2; ntl++) {
                int e = (ntp * 2 + ntl) * 8 + g4;
#pragma unroll
                for (int ks = 0; ks < 7; ks++) {
                    bfr[ntl][ks][0] = rbf_sh[p][e][ks * 8 + t4];
                    bfr[ntl][ks][1] = rbf_sh[p][e][ks * 8 + t4 + 4];
                }
            }
#pragma unroll
            for (int ks = 0; ks < 7; ks++)
#pragma unroll
                for (int mt = 0; mt < 2; mt++)
#pragma unroll
                    for (int ntl = 0; ntl < 2; ntl++)
                        mma_tf32(acc[mt][ntp * 2 + ntl], a_frag[mt][ks],
                                 bfr[ntl][ks][0], bfr[ntl][ks][1]);
        }

        // epilogue: msg = emb[type] * (acc + b_e) * cutoff  (fp32)
#pragma unroll
        for (int mt = 0; mt < 2; mt++) {
            const int d0 = wbase + mt * 16 + g4;
            const int d1 = d0 + 8;
            const float beA = mt ? be10 : be00;
            const float beB = mt ? be11 : be01;
#pragma unroll
            for (int nt = 0; nt < 8; nt++) {
                const int e0 = nt * 8 + 2 * t4;
                const int e1 = e0 + 1;
                const float w0 = w_sh[p][e0], w1 = w_sh[p][e1];
                const int  ty0 = typ_sh[p][e0], ty1 = typ_sh[p][e1];
                float em00 = __ldg(&emb[(size_t)ty0 * D_DIM + d0]);
                float em10 = __ldg(&emb[(size_t)ty1 * D_DIM + d0]);
                float em01 = __ldg(&emb[(size_t)ty0 * D_DIM + d1]);
                float em11 = __ldg(&emb[(size_t)ty1 * D_DIM + d1]);
                msg_sh[e0][d0] = em00 * (acc[mt][nt][0] + beA) * w0;
                msg_sh[e1][d0] = em10 * (acc[mt][nt][1] + beA) * w1;
                msg_sh[e0][d1] = em01 * (acc[mt][nt][2] + beB) * w0;
                msg_sh[e1][d1] = em11 * (acc[mt][nt][3] + beB) * w1;
            }
        }
        __syncthreads();                 // msg_sh ready

        for (int e = warp; e < nE; e += 4) {
            float4 v = *(const float4*)&msg_sh[e][lane * 4];
            atomicAdd((float4*)&g_acc[(size_t)dst_sh[p][e] * D_DIM + lane * 4], v);
        }
        p ^= 1;
    }
}

// ---------------------------------------------------------------------------
// Kernel 3: out = [x_nodes | g_acc] @ W_c.T + b_c  — TF32 MMA, fused K=256.
//   Persistent blocks; W_c staged once as tf32 (B fragment = W_c row-major).
//   Tile: 32 nodes x 128 dims. Warp w owns dims [32w, 32w+32):
//   32 k-steps x (2 m-tiles x 4 n-tiles) m16n8k8. Direct float2 stores.
// ---------------------------------------------------------------------------
#define XS 260     // smem row stride (tf32 words): g4*4+t4 -> conflict-free

__global__ void __launch_bounds__(128) out_kernel(
    const float* __restrict__ x_nodes,  // [N, 128]
    const float* __restrict__ W_c,      // [128, 256]
    const float* __restrict__ b_c,      // [128]
    float* __restrict__ out,            // [N, 128]
    int n_nodes)
{
    extern __shared__ unsigned ush[];
    unsigned* w_sh = ush;                 // 128 * XS
    unsigned* x_sh = ush + 128 * XS;      // 32 * XS

    const int tid  = threadIdx.x;
    const int warp = tid >> 5;
    const int lane = tid & 31;
    const int g4   = lane >> 2;
    const int t4   = lane & 3;
    const int wbase = warp * 32;

    // stage W_c once as tf32
    for (int i = tid; i < 128 * 256; i += 128) {
        int d = i >> 8, j = i & 255;
        w_sh[d * XS + j] = cvt_tf32(W_c[i]);
    }
    float2 bc[4];
#pragma unroll
    for (int nt = 0; nt < 4; nt++)
        bc[nt] = *(const float2*)&b_c[wbase + nt * 8 + 2 * t4];
    __syncthreads();

    const int num_tiles = (n_nodes + 31) / 32;
    for (int t = blockIdx.x; t < num_tiles; t += gridDim.x) {
        const int n0 = t * 32;
        const int nN = min(32, n_nodes - n0);

        // stage x tile: row n = [x_nodes | g_acc], 256 tf32 words
        for (int i = tid; i < 32 * 64; i += 128) {
            int n = i >> 6, q = i & 63;
            float4 v = make_float4(0.f, 0.f, 0.f, 0.f);
            if (n < nN) {
                v = (q < 32)
                    ? *(const float4*)&x_nodes[(size_t)(n0 + n) * 128 + q * 4]
                    : *(const float4*)&g_acc [(size_t)(n0 + n) * 128 + (q - 32) * 4];
            }
            uint4 u = make_uint4(cvt_tf32(v.x), cvt_tf32(v.y),
                                 cvt_tf32(v.z), cvt_tf32(v.w));
            *(uint4*)&x_sh[n * XS + q * 4] = u;
        }
        __syncthreads();

        float acc[2][4][4];
#pragma unroll
        for (int mt = 0; mt < 2; mt++)
#pragma unroll
            for (int nt = 0; nt < 4; nt++)
#pragma unroll
                for (int j = 0; j < 4; j++) acc[mt][nt][j] = 0.f;

#pragma unroll 4
        for (int ks = 0; ks < 32; ks++) {
            unsigned a[2][4];
#pragma unroll
            for (int mt = 0; mt < 2; mt++) {
                int base = (mt * 16 + g4) * XS + ks * 8 + t4;
                a[mt][0] = x_sh[base];
                a[mt][1] = x_sh[base + 8 * XS];
                a[mt][2] = x_sh[base + 4];
                a[mt][3] = x_sh[base + 8 * XS + 4];
            }
            unsigned b[4][2];
#pragma unroll
            for (int nt = 0; nt < 4; nt++) {
                int db = (wbase + nt * 8 + g4) * XS + ks * 8 + t4;
                b[nt][0] = w_sh[db];
                b[nt][1] = w_sh[db + 4];
            }
#pragma unroll
            for (int mt = 0; mt < 2; mt++)
#pragma unroll
                for (int nt = 0; nt < 4; nt++)
                    mma_tf32(acc[mt][nt], a[mt], b[nt][0], b[nt][1]);
        }

        // epilogue: direct float2 stores (coalesced), bias added
#pragma unroll
        for (int mt = 0; mt < 2; mt++) {
            const int r0 = n0 + mt * 16 + g4;
            const int r1 = r0 + 8;
#pragma unroll
            for (int nt = 0; nt < 4; nt++) {
                const int col = wbase + nt * 8 + 2 * t4;
                if (r0 < n_nodes)
                    *(float2*)&out[(size_t)r0 * 128 + col] =
                        make_float2(acc[mt][nt][0] + bc[nt].x,
                                    acc[mt][nt][1] + bc[nt].y);
                if (r1 < n_nodes)
                    *(float2*)&out[(size_t)r1 * 128 + col] =
                        make_float2(acc[mt][nt][2] + bc[nt].x,
                                    acc[mt][nt][3] + bc[nt].y);
            }
        }
        __syncthreads();   // x_sh reusable next iteration
    }
}

// ---------------------------------------------------------------------------
// Launch
// ---------------------------------------------------------------------------
extern "C" void kernel_launch(void* const* d_in, const int* in_sizes, int n_in,
                              void* d_out, int out_size)
{
    const int*   node_type = (const int*)  d_in[0];
    const float* x_nodes   = (const float*)d_in[1];
    const int*   src       = (const int*)  d_in[2];
    const int*   dst       = (const int*)  d_in[3];
    const float* rbf       = (const float*)d_in[4];
    const float* dist      = (const float*)d_in[5];
    const float* emb       = (const float*)d_in[6];
    const float* W_e       = (const float*)d_in[7];
    const float* b_e       = (const float*)d_in[8];
    const float* W_c       = (const float*)d_in[9];
    const float* b_c       = (const float*)d_in[10];
    float* out = (float*)d_out;

    const int n_nodes = in_sizes[0];
    const int n_edges = in_sizes[2];

    // 1) zero accumulator only (out written directly by out_kernel)
    float* g_acc_ptr = nullptr;
    cudaGetSymbolAddress((void**)&g_acc_ptr, g_acc);
    int n4 = n_nodes * D_DIM / 4;
    zero_kernel<<<(n4 + 255) / 256, 256>>>((float4*)g_acc_ptr, n4);

    // 2) edge projection (TF32 MMA) + gather-multiply-scatter
    edge_kernel<<<444, 128>>>(rbf, dist, src, dst, node_type, emb, W_e, b_e, n_edges);

    // 3) fused combine GEMM (TF32 MMA, K=256, direct store)
    size_t shmem = (size_t)(128 * XS + 32 * XS) * sizeof(unsigned);
    cudaFuncSetAttribute(out_kernel, cudaFuncAttributeMaxDynamicSharedMemorySize, (int)shmem);
    out_kernel<<<152, 128, shmem>>>(x_nodes, W_c, b_c, out, n_nodes);
}

// round 14
// speedup vs baseline: 1.4160x; 1.4160x over previous
#include <cuda_runtime.h>
#include <cuda_bf16.h>

#define D_DIM     128
#define N_RBF     50
#define KP        56            // MMA K padded to 7 x 8
#define E_TILE    32            // edges per tile
#define RBF_STRIDE 60           // conflict-free B-fragment banks
#define MSG_STRIDE 132          // conflict-free epilogue STS
#define MAX_NODES 50000
#define CUTOFF_F  5.0f
#define PI_OVER_CUTOFF 0.62831853071795864769f

// scatter-sum accumulator (device global scratch; no cudaMalloc allowed)
__device__ float g_acc[(size_t)MAX_NODES * D_DIM];

// ---------------------------------------------------------------------------
// helpers
// ---------------------------------------------------------------------------
__device__ __forceinline__ unsigned cvt_tf32(float x) {
    unsigned r;
    asm("cvt.rna.tf32.f32 %0, %1;" : "=r"(r) : "f"(x));
    return r;
}
__device__ __forceinline__ void mma_tf32(float* acc, const unsigned* a,
                                         unsigned b0, unsigned b1) {
    asm("mma.sync.aligned.m16n8k8.row.col.f32.tf32.tf32.f32 "
        "{%0,%1,%2,%3},{%4,%5,%6,%7},{%8,%9},{%0,%1,%2,%3};"
        : "+f"(acc[0]), "+f"(acc[1]), "+f"(acc[2]), "+f"(acc[3])
        : "r"(a[0]), "r"(a[1]), "r"(a[2]), "r"(a[3]), "r"(b0), "r"(b1));
}

// ---------------------------------------------------------------------------
// Kernel 1: zero both accumulator and output
// ---------------------------------------------------------------------------
__global__ void zero2_kernel(float4* a, float4* b, int n4) {
    int i = blockIdx.x * blockDim.x + threadIdx.x;
    if (i < n4) {
        a[i] = make_float4(0.f, 0.f, 0.f, 0.f);
        b[i] = make_float4(0.f, 0.f, 0.f, 0.f);
    }
}

// ---------------------------------------------------------------------------
// Kernel 2: edge kernel, TF32 MMA, double-buffered (R11 proven version).
// ---------------------------------------------------------------------------
__global__ void __launch_bounds__(128) edge_kernel(
    const float* __restrict__ rbf,       // [E, 50]
    const float* __restrict__ dist,      // [E]
    const int*   __restrict__ src,       // [E]
    const int*   __restrict__ dst,       // [E]
    const int*   __restrict__ node_type, // [N]
    const float* __restrict__ emb,       // [100, 128]
    const float* __restrict__ W_e,       // [128, 50]
    const float* __restrict__ b_e,       // [128]
    int n_edges)
{
    __shared__ unsigned rbf_sh[2][E_TILE][RBF_STRIDE];
    __shared__ float    msg_sh[E_TILE][MSG_STRIDE];
    __shared__ float    w_sh[2][E_TILE];
    __shared__ int      dst_sh[2][E_TILE];
    __shared__ int      typ_sh[2][E_TILE];

    const int tid  = threadIdx.x;
    const int warp = tid >> 5;
    const int lane = tid & 31;
    const int g4   = lane >> 2;
    const int t4   = lane & 3;
    const int wbase = warp * 32;

    unsigned a_frag[2][7][4];
#pragma unroll
    for (int mt = 0; mt < 2; mt++)
#pragma unroll
        for (int ks = 0; ks < 7; ks++)
#pragma unroll
            for (int j = 0; j < 4; j++) {
                int d = wbase + mt * 16 + g4 + ((j & 1) ? 8 : 0);
                int k = ks * 8 + t4 + ((j >= 2) ? 4 : 0);
                float v = (k < N_RBF) ? W_e[d * N_RBF + k] : 0.f;
                a_frag[mt][ks][j] = cvt_tf32(v);
            }
    float be00 = b_e[wbase + g4];
    float be01 = b_e[wbase + g4 + 8];
    float be10 = b_e[wbase + 16 + g4];
    float be11 = b_e[wbase + 16 + g4 + 8];

    const int num_tiles = (n_edges + E_TILE - 1) / E_TILE;

    auto load_tile = [&](int t, int b) {
        const int e0 = t * E_TILE;
        const int nE = min(E_TILE, n_edges - e0);
        for (int i = tid; i < E_TILE * KP; i += 128) {
            int e = i / KP;
            int k = i - e * KP;
            float v = (k < N_RBF && e < nE) ? rbf[(size_t)(e0 + e) * N_RBF + k] : 0.f;
            rbf_sh[b][e][k] = cvt_tf32(v);
        }
        if (tid < E_TILE) {
            bool valid = tid < nE;
            float dd = valid ? dist[e0 + tid] : 1e9f;
            float w  = 0.5f * (__cosf(dd * PI_OVER_CUTOFF) + 1.0f);
            w_sh[b][tid]   = (dd < CUTOFF_F) ? w : 0.f;
            typ_sh[b][tid] = valid ? node_type[src[e0 + tid]] : 0;
            dst_sh[b][tid] = valid ? dst[e0 + tid] : 0;
        }
    };

    int p = 0;
    if (blockIdx.x < num_tiles) load_tile(blockIdx.x, 0);

    for (int tile = blockIdx.x; tile < num_tiles; tile += gridDim.x) {
        const int nE = min(E_TILE, n_edges - tile * E_TILE);

        __syncthreads();                 // buf[p] ready; msg_sh free

        const int next = tile + gridDim.x;
        if (next < num_tiles) load_tile(next, p ^ 1);   // overlap with MMA

        float acc[2][4][4];
#pragma unroll
        for (int mt = 0; mt < 2; mt++)
#pragma unroll
            for (int nt = 0; nt < 4; nt++)
#pragma unroll
                for (int j = 0; j < 4; j++) acc[mt][nt][j] = 0.f;

#pragma unroll
        for (int ntp = 0; ntp < 2; ntp++) {
            unsigned bfr[2][7][2];
#pragma unroll
            for (int ntl = 0; ntl < 2; ntl++) {
                int e = (ntp * 2 + ntl) * 8 + g4;
#pragma unroll
                for (int ks = 0; ks < 7; ks++) {
                    bfr[ntl][ks][0] = rbf_sh[p][e][ks * 8 + t4];
                    bfr[ntl][ks][1] = rbf_sh[p][e][ks * 8 + t4 + 4];
                }
            }
#pragma unroll
            for (int ks = 0; ks < 7; ks++)
#pragma unroll
                for (int mt = 0; mt < 2; mt++)
#pragma unroll
                    for (int ntl = 0; ntl < 2; ntl++)
                        mma_tf32(acc[mt][ntp * 2 + ntl], a_frag[mt][ks],
                                 bfr[ntl][ks][0], bfr[ntl][ks][1]);
        }

        // epilogue: msg = emb[type] * (acc + b_e) * cutoff  (fp32)
#pragma unroll
        for (int mt = 0; mt < 2; mt++) {
            const int d0 = wbase + mt * 16 + g4;
            const int d1 = d0 + 8;
            const float beA = mt ? be10 : be00;
            const float beB = mt ? be11 : be01;
#pragma unroll
            for (int nt = 0; nt < 4; nt++) {
                const int e0 = nt * 8 + 2 * t4;
                const int e1 = e0 + 1;
                const float w0 = w_sh[p][e0], w1 = w_sh[p][e1];
                const int  ty0 = typ_sh[p][e0], ty1 = typ_sh[p][e1];
                float em00 = __ldg(&emb[(size_t)ty0 * D_DIM + d0]);
                float em10 = __ldg(&emb[(size_t)ty1 * D_DIM + d0]);
                float em01 = __ldg(&emb[(size_t)ty0 * D_DIM + d1]);
                float em11 = __ldg(&emb[(size_t)ty1 * D_DIM + d1]);
                msg_sh[e0][d0] = em00 * (acc[mt][nt][0] + beA) * w0;
                msg_sh[e1][d0] = em10 * (acc[mt][nt][1] + beA) * w1;
                msg_sh[e0][d1] = em01 * (acc[mt][nt][2] + beB) * w0;
                msg_sh[e1][d1] = em11 * (acc[mt][nt][3] + beB) * w1;
            }
        }
        __syncthreads();                 // msg_sh ready

        for (int e = warp; e < nE; e += 4) {
            float4 v = *(const float4*)&msg_sh[e][lane * 4];
            atomicAdd((float4*)&g_acc[(size_t)dst_sh[p][e] * D_DIM + lane * 4], v);
        }
        p ^= 1;
    }
}

// ---------------------------------------------------------------------------
// Kernel 3: out += xsrc_h @ Wc[:, h*128:(h+1)*128].T  — TF32 MMA, half-K split.
//   Block color h = blockIdx.x & 1 (0: x_nodes + bias, 1: g_acc).
//   w_sh 66KB + x_sh 16.5KB -> 2 blocks/SM (2 warps/SMSP latency hiding).
//   Warp w owns dims [32w, 32w+32); 16 k-steps x 8 MMAs per tile.
//   Halves combined with direct float2 atomicAdd into zeroed out.
// ---------------------------------------------------------------------------
#define W2S 132    // smem row stride (words): fragment banks g4*4+t4, conflict-free

__global__ void __launch_bounds__(128) out_kernel(
    const float* __restrict__ x_nodes,  // [N, 128]
    const float* __restrict__ W_c,      // [128, 256]
    const float* __restrict__ b_c,      // [128]
    float* __restrict__ out,            // [N, 128]
    int n_nodes)
{
    extern __shared__ unsigned ush[];
    unsigned* w_sh = ush;                 // 128 * W2S
    unsigned* x_sh = ush + 128 * W2S;     // 32 * W2S

    const int tid  = threadIdx.x;
    const int warp = tid >> 5;
    const int lane = tid & 31;
    const int g4   = lane >> 2;
    const int t4   = lane & 3;
    const int wbase = warp * 32;
    const int h    = blockIdx.x & 1;
    const float* xsrc = h ? g_acc : x_nodes;

    // stage this K-half of W_c as tf32: w_sh[d][j] = Wc[d][h*128+j]
    for (int i = tid; i < 128 * 128; i += 128) {
        int d = i >> 7, j = i & 127;
        w_sh[d * W2S + j] = cvt_tf32(W_c[d * 256 + h * 128 + j]);
    }
    float2 bc[4];
#pragma unroll
    for (int nt = 0; nt < 4; nt++) {
        float2 v = *(const float2*)&b_c[wbase + nt * 8 + 2 * t4];
        bc[nt] = h ? make_float2(0.f, 0.f) : v;
    }
    __syncthreads();

    const int num_tiles = (n_nodes + 31) / 32;
    const int bstride = gridDim.x >> 1;

    for (int t = (blockIdx.x >> 1); t < num_tiles; t += bstride) {
        const int n0 = t * 32;
        const int nN = min(32, n_nodes - n0);

        // stage x tile as tf32: 32 rows x 128 words
        for (int i = tid; i < 32 * 32; i += 128) {
            int n = i >> 5, q = i & 31;
            float4 v = make_float4(0.f, 0.f, 0.f, 0.f);
            if (n < nN)
                v = *(const float4*)&xsrc[(size_t)(n0 + n) * 128 + q * 4];
            uint4 u = make_uint4(cvt_tf32(v.x), cvt_tf32(v.y),
                                 cvt_tf32(v.z), cvt_tf32(v.w));
            *(uint4*)&x_sh[n * W2S + q * 4] = u;
        }
        __syncthreads();

        float acc[2][4][4];
#pragma unroll
        for (int mt = 0; mt < 2; mt++)
#pragma unroll
            for (int nt = 0; nt < 4; nt++)
#pragma unroll
                for (int j = 0; j < 4; j++) acc[mt][nt][j] = 0.f;

#pragma unroll 4
        for (int ks = 0; ks < 16; ks++) {
            unsigned a[2][4];
#pragma unroll
            for (int mt = 0; mt < 2; mt++) {
                int base = (mt * 16 + g4) * W2S + ks * 8 + t4;
                a[mt][0] = x_sh[base];
                a[mt][1] = x_sh[base + 8 * W2S];
                a[mt][2] = x_sh[base + 4];
                a[mt][3] = x_sh[base + 8 * W2S + 4];
            }
            unsigned b[4][2];
#pragma unroll
            for (int nt = 0; nt < 4; nt++) {
                int db = (wbase + nt * 8 + g4) * W2S + ks * 8 + t4;
                b[nt][0] = w_sh[db];
                b[nt][1] = w_sh[db + 4];
            }
#pragma unroll
            for (int mt = 0; mt < 2; mt++)
#pragma unroll
                for (int nt = 0; nt < 4; nt++)
                    mma_tf32(acc[mt][nt], a[mt], b[nt][0], b[nt][1]);
        }

        // epilogue: direct float2 atomic combine (out pre-zeroed)
#pragma unroll
        for (int mt = 0; mt < 2; mt++) {
            const int r0 = n0 + mt * 16 + g4;
            const int r1 = r0 + 8;
#pragma unroll
            for (int nt = 0; nt < 4; nt++) {
                const int col = wbase + nt * 8 + 2 * t4;
                if (r0 < n_nodes)
                    atomicAdd((float2*)&out[(size_t)r0 * 128 + col],
                              make_float2(acc[mt][nt][0] + bc[nt].x,
                                          acc[mt][nt][1] + bc[nt].y));
                if (r1 < n_nodes)
                    atomicAdd((float2*)&out[(size_t)r1 * 128 + col],
                              make_float2(acc[mt][nt][2] + bc[nt].x,
                                          acc[mt][nt][3] + bc[nt].y));
            }
        }
        __syncthreads();   // x_sh reusable next iteration
    }
}

// ---------------------------------------------------------------------------
// Launch
// ---------------------------------------------------------------------------
extern "C" void kernel_launch(void* const* d_in, const int* in_sizes, int n_in,
                              void* d_out, int out_size)
{
    const int*   node_type = (const int*)  d_in[0];
    const float* x_nodes   = (const float*)d_in[1];
    const int*   src       = (const int*)  d_in[2];
    const int*   dst       = (const int*)  d_in[3];
    const float* rbf       = (const float*)d_in[4];
    const float* dist      = (const float*)d_in[5];
    const float* emb       = (const float*)d_in[6];
    const float* W_e       = (const float*)d_in[7];
    const float* b_e       = (const float*)d_in[8];
    const float* W_c       = (const float*)d_in[9];
    const float* b_c       = (const float*)d_in[10];
    float* out = (float*)d_out;

    const int n_nodes = in_sizes[0];
    const int n_edges = in_sizes[2];

    // 1) zero accumulator + output together
    float* g_acc_ptr = nullptr;
    cudaGetSymbolAddress((void**)&g_acc_ptr, g_acc);
    int n4 = n_nodes * D_DIM / 4;
    zero2_kernel<<<(n4 + 255) / 256, 256>>>((float4*)g_acc_ptr, (float4*)out, n4);

    // 2) edge projection (TF32 MMA) + gather-multiply-scatter
    edge_kernel<<<592, 128>>>(rbf, dist, src, dst, node_type, emb, W_e, b_e, n_edges);

    // 3) combine GEMM (TF32 MMA, half-K per block color, atomic combine)
    size_t shmem = (size_t)(128 * W2S + 32 * W2S) * sizeof(unsigned);
    cudaFuncSetAttribute(out_kernel, cudaFuncAttributeMaxDynamicSharedMemorySize, (int)shmem);
    out_kernel<<<296, 128, shmem>>>(x_nodes, W_c, b_c, out, n_nodes);
}